// round 1
// baseline (speedup 1.0000x reference)
#include <cuda_runtime.h>

// Problem constants (shapes fixed by the dataset):
//   x: (32, 1, 64, 8000) fp32, a: (64,), w: (64,)
//   y[b,f,t] = | x[t] - C*w * sum_{d=1}^{498} a^{d-1} * x_edge[t-d] |
//   C = (1-a)/(1-a^498), edge pad: x[j<0] -> x[0]
#define T_LEN 8000
#define WIN   498          // K-1
#define NSUB  32           // sub-chunks per row (phase-B workers)
#define LSUB  (T_LEN/NSUB) // 250
#define BLOCK 128

__global__ __launch_bounds__(BLOCK, 3)
void willmore_kernel(const float* __restrict__ x,
                     const float* __restrict__ a,
                     const float* __restrict__ w,
                     float* __restrict__ out,
                     int F) {
    extern __shared__ float sm[];
    float* xs = sm;           // [T_LEN] input row
    float* ys = sm + T_LEN;   // [T_LEN] output row

    const int row = blockIdx.x;           // row = b*F + f
    const int f   = row % F;
    const float* __restrict__ xrow = x   + (size_t)row * T_LEN;
    float*       __restrict__ orow = out + (size_t)row * T_LEN;

    // ---- per-channel constants (fp32 repeated squaring; ~1e-6 rel err) ----
    const float af = __ldg(&a[f]);
    const float wf = __ldg(&w[f]);
    float p498;
    {
        float p = 1.0f, base = af;
        int e = WIN;                       // a^498
        while (e) { if (e & 1) p *= base; base *= base; e >>= 1; }
        p498 = p;
    }
    const float Cw = (1.0f - af) / (1.0f - p498) * wf;

    // ---- phase A: coalesced row load into smem ----
    {
        const float4* __restrict__ x4 = (const float4*)xrow;
        float4* xs4 = (float4*)xs;
        #pragma unroll
        for (int i = threadIdx.x; i < T_LEN / 4; i += BLOCK)
            xs4[i] = x4[i];
    }
    __syncthreads();

    // ---- phase B: 32 independent chunk recurrences ----
    if (threadIdx.x < NSUB) {
        const int t0 = threadIdx.x * LSUB;

        // warm-up: S = sum_{d=1}^{WIN} a^{d-1} * xs[clamp(t0-d)]
        // Horner forward over j = t0-WIN .. t0-1:  S = a*S + xs[j]
        float S = 0.0f;
        #pragma unroll 6
        for (int j = t0 - WIN; j < t0; ++j) {
            int idx = j < 0 ? 0 : j;
            S = fmaf(af, S, xs[idx]);
        }

        // main sliding window over this chunk
        #pragma unroll 5
        for (int s = 0; s < LSUB; ++s) {
            const int t = t0 + s;
            const float xt = xs[t];
            ys[t] = fabsf(fmaf(-Cw, S, xt));
            int ti = t - WIN; ti = ti < 0 ? 0 : ti;
            const float u = fmaf(-p498, xs[ti], xt);  // x[t] - a^498 * x[t-498]
            S = fmaf(af, S, u);
        }
    }
    __syncthreads();

    // ---- phase C: coalesced row store ----
    {
        const float4* ys4 = (const float4*)ys;
        float4* __restrict__ o4 = (float4*)orow;
        #pragma unroll
        for (int i = threadIdx.x; i < T_LEN / 4; i += BLOCK)
            o4[i] = ys4[i];
    }
}

extern "C" void kernel_launch(void* const* d_in, const int* in_sizes, int n_in,
                              void* d_out, int out_size) {
    const float* x = (const float*)d_in[0];
    const float* a = (const float*)d_in[1];
    const float* w = (const float*)d_in[2];
    float* out = (float*)d_out;

    const int F = in_sizes[1];                // 64
    const int rows = in_sizes[0] / T_LEN;     // B*F = 2048
    const int smem = 2 * T_LEN * (int)sizeof(float);  // 64 KB

    cudaFuncSetAttribute(willmore_kernel,
                         cudaFuncAttributeMaxDynamicSharedMemorySize, smem);
    willmore_kernel<<<rows, BLOCK, smem>>>(x, a, w, out, F);
}

// round 3
// speedup vs baseline: 1.4049x; 1.4049x over previous
#include <cuda_runtime.h>

// x: (32,1,64,8000) fp32, a:(64,), w:(64,)
// y[b,f,t] = | x[t] - Cw * S_t |,  S_t = sum_{d=1}^{498} a^{d-1} x_edge[t-d]
// Cw = w*(1-a)/(1-a^498), edge pad x[j<0] -> x[0]
#define T_LEN 8000
#define WIN   498
#define NSUB  64
#define LSUB  125          // T_LEN / NSUB
#define BLOCK 256

__device__ __forceinline__ float ipowf(float base, int e) {
    float p = 1.0f;
    while (e) { if (e & 1) p *= base; base *= base; e >>= 1; }
    return p;
}

__global__ __launch_bounds__(BLOCK, 3)
void willmore_kernel(const float* __restrict__ x,
                     const float* __restrict__ a,
                     const float* __restrict__ w,
                     float* __restrict__ out,
                     int F) {
    extern __shared__ float sm[];
    float* xs = sm;                 // [T_LEN]
    float* ys = sm + T_LEN;         // [T_LEN]

    const int row = blockIdx.x;     // b*F + f
    const int f   = row % F;
    const float* __restrict__ xrow = x   + (size_t)row * T_LEN;
    float*       __restrict__ orow = out + (size_t)row * T_LEN;

    const float af = __ldg(&a[f]);
    const float wf = __ldg(&w[f]);
    const float p498 = ipowf(af, WIN);
    const float Cw = (1.0f - af) / (1.0f - p498) * wf;

    // ---- phase A: coalesced load row -> smem ----
    {
        const float4* __restrict__ x4 = (const float4*)xrow;
        float4* xs4 = (float4*)xs;
        #pragma unroll
        for (int i = threadIdx.x; i < T_LEN / 4; i += BLOCK)
            xs4[i] = x4[i];
    }
    __syncthreads();

    const int tid = threadIdx.x;

    // ---- phase B: per-chunk warm-up (4 independent clamped Horner chains)
    //      then O(1)/step sliding recurrence over the chunk ----
    if (tid < NSUB) {
        const int t0 = tid * LSUB;

        // Window j in [t0-498, t0), weight a^(t0-1-j), x_edge[j<0] = x[0].
        // Split into 4 contiguous segments: 124 | 125 | 125 | 124.
        const int c0 = t0 - 498;
        const int c1 = t0 - 374;
        const int c2 = t0 - 249;
        const int c3 = t0 - 124;

        float s0 = 0.f, s1 = 0.f, s2 = 0.f, s3 = 0.f;
        #pragma unroll 5
        for (int m = 0; m < 125; ++m) {
            int j1 = c1 + m; j1 = j1 < 0 ? 0 : j1;
            int j2 = c2 + m; j2 = j2 < 0 ? 0 : j2;
            s1 = fmaf(af, s1, xs[j1]);
            s2 = fmaf(af, s2, xs[j2]);
            if (m < 124) {
                int j0 = c0 + m; j0 = j0 < 0 ? 0 : j0;
                int j3 = c3 + m; j3 = j3 < 0 ? 0 : j3;
                s0 = fmaf(af, s0, xs[j0]);
                s3 = fmaf(af, s3, xs[j3]);
            }
        }
        // S = ((s0*a^125 + s1)*a^125 + s2)*a^124 + s3
        const float a125 = ipowf(af, 125);
        const float a124 = ipowf(af, 124);
        float S = fmaf(fmaf(fmaf(s0, a125, s1), a125, s2), a124, s3);

        // main sliding loop over this chunk
        #pragma unroll 5
        for (int s = 0; s < LSUB; ++s) {
            const int t = t0 + s;
            const float xt = xs[t];
            ys[t] = fabsf(fmaf(-Cw, S, xt));
            int j = t - WIN; j = j < 0 ? 0 : j;
            S = fmaf(af, S, fmaf(-p498, xs[j], xt));
        }
    }
    __syncthreads();

    // ---- phase C: coalesced store ----
    {
        const float4* ys4 = (const float4*)ys;
        float4* __restrict__ o4 = (float4*)orow;
        #pragma unroll
        for (int i = threadIdx.x; i < T_LEN / 4; i += BLOCK)
            o4[i] = ys4[i];
    }
}

extern "C" void kernel_launch(void* const* d_in, const int* in_sizes, int n_in,
                              void* d_out, int out_size) {
    const float* x = (const float*)d_in[0];
    const float* a = (const float*)d_in[1];
    const float* w = (const float*)d_in[2];
    float* out = (float*)d_out;

    const int F = in_sizes[1];                 // 64
    const int rows = in_sizes[0] / T_LEN;      // 2048
    const int smem = 2 * T_LEN * (int)sizeof(float);   // 64 KB

    cudaFuncSetAttribute(willmore_kernel,
                         cudaFuncAttributeMaxDynamicSharedMemorySize, smem);
    willmore_kernel<<<rows, BLOCK, smem>>>(x, a, w, out, F);
}

// round 4
// speedup vs baseline: 2.0308x; 1.4456x over previous
#include <cuda_runtime.h>

// x: (32,1,64,8000) fp32, a:(64,), w:(64,)
// y[b,f,t] = | x[t] - Cw * S_t |,  S_t = sum_{d=1}^{498} a^{d-1} x_edge[t-d]
// Cw = w*(1-a)/(1-a^498), edge pad x[j<0] -> x[0]
#define T_LEN 8000
#define WIN   498
#define NSUB  320
#define LSUB  25           // T_LEN / NSUB ; gcd(25,32)=1 -> conflict-free LDS
#define QF    19           // full chunks inside window (19*25=475)
#define BLOCK 320

__device__ __forceinline__ float ipowf(float base, int e) {
    float p = 1.0f;
    while (e) { if (e & 1) p *= base; base *= base; e >>= 1; }
    return p;
}

__global__ __launch_bounds__(BLOCK, 3)
void willmore_kernel(const float* __restrict__ x,
                     const float* __restrict__ a,
                     const float* __restrict__ w,
                     float* __restrict__ out,
                     int F) {
    extern __shared__ float sm[];
    float* xs = sm;                 // [T_LEN]
    float* ys = sm + T_LEN;         // [T_LEN]
    float* sG = sm + 2 * T_LEN;     // [NSUB] full-chunk Horner sums
    float* sH = sG + NSUB;          // [NSUB] last-23 Horner sums

    const int row = blockIdx.x;     // b*F + f
    const int f   = row % F;
    const float* __restrict__ xrow = x   + (size_t)row * T_LEN;
    float*       __restrict__ orow = out + (size_t)row * T_LEN;

    const float af = __ldg(&a[f]);
    const float wf = __ldg(&w[f]);
    const float p498 = ipowf(af, WIN);
    const float Cw = (1.0f - af) / (1.0f - p498) * wf;
    const float a23 = ipowf(af, 23);
    const float a24 = a23 * af;
    const float a25 = a24 * af;

    // ---- phase A: coalesced load row -> smem ----
    {
        const float4* __restrict__ x4 = (const float4*)xrow;
        float4* xs4 = (float4*)xs;
        #pragma unroll
        for (int i = threadIdx.x; i < T_LEN / 4; i += BLOCK)
            xs4[i] = x4[i];
    }
    __syncthreads();

    const int tid = threadIdx.x;
    const int t0  = tid * LSUB;

    // ---- phase B1: per-chunk Horner over 25 samples ----
    // G_k = sum_{s=0}^{24} a^(24-s) * x[t0+s]
    float xf0 = 0.f, xf1 = 0.f;
    float g = 0.f;
    #pragma unroll
    for (int s = 0; s < LSUB; ++s) {
        const float v = xs[t0 + s];
        if (s == 0) xf0 = v;
        if (s == 1) xf1 = v;
        g = fmaf(af, g, v);
    }
    sG[tid] = g;
    // H_k = G_k - a^24*x[t0] - a^23*x[t0+1]  (last 23 samples only)
    sH[tid] = fmaf(-a24, xf0, fmaf(-a23, xf1, g));
    __syncthreads();

    // ---- phase B2: O(QF) warm-up combine, then sliding recurrence ----
    {
        float S;
        if (tid >= QF + 1) {
            // S = a^475*H_{i-20} + sum_{m=1}^{19} a^(25*(m-1)) * G_{i-m}
            S = sH[tid - (QF + 1)];
            #pragma unroll
            for (int j = QF; j >= 1; --j)       // adds G_{tid-19} ... G_{tid-1}
                S = fmaf(S, a25, sG[tid - j]);
        } else {
            // pad region: x[j<0] = x[0]; geometric tail then ascend over real chunks
            const float x0v = xs[0];
            const float atail = ipowf(af, WIN - LSUB * tid); // a^(498-25*tid)
            S = x0v * (1.0f - atail) / (1.0f - af);
            for (int k = 0; k < tid; ++k)        // ASCENDING: farthest first
                S = fmaf(S, a25, sG[k]);
        }

        if (t0 >= WIN) {
            // no clamping possible (t - 498 >= 2)
            #pragma unroll
            for (int s = 0; s < LSUB; ++s) {
                const int t = t0 + s;
                const float xt = xs[t];
                ys[t] = fabsf(fmaf(-Cw, S, xt));
                S = fmaf(af, S, fmaf(-p498, xs[t - WIN], xt));
            }
        } else {
            #pragma unroll
            for (int s = 0; s < LSUB; ++s) {
                const int t = t0 + s;
                const float xt = xs[t];
                ys[t] = fabsf(fmaf(-Cw, S, xt));
                int j = t - WIN; j = j < 0 ? 0 : j;
                S = fmaf(af, S, fmaf(-p498, xs[j], xt));
            }
        }
    }
    __syncthreads();

    // ---- phase C: coalesced store ----
    {
        const float4* ys4 = (const float4*)ys;
        float4* __restrict__ o4 = (float4*)orow;
        #pragma unroll
        for (int i = threadIdx.x; i < T_LEN / 4; i += BLOCK)
            o4[i] = ys4[i];
    }
}

extern "C" void kernel_launch(void* const* d_in, const int* in_sizes, int n_in,
                              void* d_out, int out_size) {
    const float* x = (const float*)d_in[0];
    const float* a = (const float*)d_in[1];
    const float* w = (const float*)d_in[2];
    float* out = (float*)d_out;

    const int F = in_sizes[1];                 // 64
    const int rows = in_sizes[0] / T_LEN;      // 2048
    const int smem = (2 * T_LEN + 2 * NSUB) * (int)sizeof(float); // 66560 B

    cudaFuncSetAttribute(willmore_kernel,
                         cudaFuncAttributeMaxDynamicSharedMemorySize, smem);
    willmore_kernel<<<rows, BLOCK, smem>>>(x, a, w, out, F);
}

// round 5
// speedup vs baseline: 2.2899x; 1.1275x over previous
#include <cuda_runtime.h>

// x: (32,1,64,8000) fp32, a:(64,), w:(64,)
// y[b,f,t] = | x[t] - Cw * S_t |,  S_t = sum_{d=1}^{498} a^{d-1} x_edge[t-d]
// Cw = w*(1-a)/(1-a^498), edge pad x[j<0] -> x[0]
//
// Each block processes a 4000-sample half-row with a 500-sample halo in smem,
// so edge padding is materialized once and compute is clamp-free.
#define T_LEN  8000
#define HALF_T 4000
#define HALO   500
#define XS_LEN 4500        // HALO + HALF_T
#define WIN    498
#define LSUB   25          // samples per worker chunk (coprime with 32)
#define NSUB   160         // worker threads (NSUB*LSUB = HALF_T)
#define NG     179         // chunk sums needed (workers' chunks + 19 ahead)
#define BLOCK  192

__device__ __forceinline__ float ipowf(float base, int e) {
    float p = 1.0f;
    while (e) { if (e & 1) p *= base; base *= base; e >>= 1; }
    return p;
}

__global__ __launch_bounds__(BLOCK, 6)
void willmore_kernel(const float* __restrict__ x,
                     const float* __restrict__ a,
                     const float* __restrict__ w,
                     float* __restrict__ out,
                     int F) {
    extern __shared__ float sm[];
    float* xs  = sm;                    // [XS_LEN]  halo + half-row
    float* ys  = sm + XS_LEN;           // [HALF_T]  outputs
    float* sG  = sm + XS_LEN + HALF_T;  // [NG] full-chunk Horner sums
    float* sHd = sG + 180;              // [NG] head-23 Horner sums

    const int row    = blockIdx.x >> 1;
    const int half   = blockIdx.x & 1;
    const int t_base = half * HALF_T;
    const int f      = row % F;
    const float* __restrict__ xrow = x + (size_t)row * T_LEN;
    float*       __restrict__ orow = out + (size_t)row * T_LEN + t_base;

    const float af = __ldg(&a[f]);
    const float wf = __ldg(&w[f]);
    const float p498 = ipowf(af, WIN);
    const float Cw = (1.0f - af) / (1.0f - p498) * wf;
    const float a23 = ipowf(af, 23);
    const float a25 = a23 * af * af;

    // ---- phase A: load halo + half-row (edge pad materialized) ----
    {
        float4* xs4 = (float4*)xs;
        const float4* __restrict__ src4 =
            (const float4*)(xrow + t_base - HALO);     // aligned: t_base-500 ∈ {-500, 3500}
        if (half == 0) {
            const float x0v = __ldg(&xrow[0]);
            const float4 pad4 = make_float4(x0v, x0v, x0v, x0v);
            #pragma unroll
            for (int i = threadIdx.x; i < XS_LEN / 4; i += BLOCK)
                xs4[i] = (i < HALO / 4) ? pad4 : src4[i];
        } else {
            #pragma unroll
            for (int i = threadIdx.x; i < XS_LEN / 4; i += BLOCK)
                xs4[i] = src4[i];
        }
    }
    __syncthreads();

    const int tid = threadIdx.x;

    // ---- phase B1: chunk Horner sums over xs grid offset +2 ----
    // G_k = sum_{s=0}^{24} a^(24-s) xs[25k+2+s];  Hd_k = first 23 terms
    if (tid < NG) {
        const int base = 25 * tid + 2;
        float g = 0.f;
        #pragma unroll
        for (int s = 0; s < 23; ++s)
            g = fmaf(af, g, xs[base + s]);
        const float hd = g;
        g = fmaf(af, g, xs[base + 23]);
        g = fmaf(af, g, xs[base + 24]);
        sG[tid]  = g;
        sHd[tid] = hd;
    }
    __syncthreads();

    // ---- phase B2: warm-up combine + sliding recurrence (clamp-free) ----
    if (tid < NSUB) {
        // S = Hd_{tid+19} + a^23 * sum_{m=0}^{18} a^(25m) G_{tid+18-m}
        float T = sG[tid];                       // farthest chunk
        #pragma unroll
        for (int m = 1; m <= 18; ++m)
            T = fmaf(a25, T, sG[tid + m]);
        float S = fmaf(a23, T, sHd[tid + 19]);

        const int p0 = 25 * tid;
        #pragma unroll
        for (int s = 0; s < LSUB; ++s) {
            const float xt = xs[p0 + HALO + s];          // x[t]
            ys[p0 + s] = fabsf(fmaf(-Cw, S, xt));
            const float xo = xs[p0 + 2 + s];             // x[t-498]
            S = fmaf(af, S, fmaf(-p498, xo, xt));
        }
    }
    __syncthreads();

    // ---- phase C: coalesced store ----
    {
        const float4* ys4 = (const float4*)ys;
        float4* __restrict__ o4 = (float4*)orow;
        #pragma unroll
        for (int i = threadIdx.x; i < HALF_T / 4; i += BLOCK)
            o4[i] = ys4[i];
    }
}

extern "C" void kernel_launch(void* const* d_in, const int* in_sizes, int n_in,
                              void* d_out, int out_size) {
    const float* x = (const float*)d_in[0];
    const float* a = (const float*)d_in[1];
    const float* w = (const float*)d_in[2];
    float* out = (float*)d_out;

    const int F = in_sizes[1];                  // 64
    const int rows = in_sizes[0] / T_LEN;       // 2048
    const int smem = (XS_LEN + HALF_T + 2 * 180) * (int)sizeof(float); // 35440 B

    cudaFuncSetAttribute(willmore_kernel,
                         cudaFuncAttributeMaxDynamicSharedMemorySize, smem);
    willmore_kernel<<<rows * 2, BLOCK, smem>>>(x, a, w, out, F);
}

// round 6
// speedup vs baseline: 3.0268x; 1.3218x over previous
#include <cuda_runtime.h>
#include <cstdint>

// x: (32,1,64,8000) fp32, a:(64,), w:(64,)
// y[b,f,t] = | x[t] - Cw * S_t |,  S_t = sum_{d=1}^{498} a^{d-1} x_edge[t-d]
// Cw = w*(1-a)/(1-a^498), edge pad x[j<0] -> x[0]
//
// Half-row blocks (4000 samples + 500 halo in smem). Bulk-async load/store,
// chunked parallel warm-up, register-cached chunk windows.
#define T_LEN  8000
#define HALF_T 4000
#define HALO   500
#define XS_LEN 4500
#define WIN    498
#define LSUB   25
#define NSUB   160
#define NG     179
#define BLOCK  192

__device__ __forceinline__ float ipowf(float base, int e) {
    float p = 1.0f;
    while (e) { if (e & 1) p *= base; base *= base; e >>= 1; }
    return p;
}

__global__ __launch_bounds__(BLOCK, 5)
void willmore_kernel(const float* __restrict__ x,
                     const float* __restrict__ a,
                     const float* __restrict__ w,
                     float* __restrict__ out,
                     int F) {
    extern __shared__ float sm[];
    float* xs  = sm;                          // [4500]
    float* ys  = sm + XS_LEN;                 // [4000]
    float* sG  = sm + XS_LEN + HALF_T;        // [180]
    float* sHd = sG + 180;                    // [180]
    uint32_t mbar = (uint32_t)__cvta_generic_to_shared(sHd + 180); // 16B-aligned

    const int tid    = threadIdx.x;
    const int row    = blockIdx.x >> 1;
    const int half   = blockIdx.x & 1;
    const int t_base = half * HALF_T;
    const int f      = row % F;
    const float* __restrict__ xrow = x + (size_t)row * T_LEN;
    float*       __restrict__ orow = out + (size_t)row * T_LEN + t_base;

    // ---- phase A: bulk async copy GMEM -> smem, mbarrier completion ----
    if (tid == 0) {
        asm volatile("mbarrier.init.shared.b64 [%0], %1;"
                     :: "r"(mbar), "r"(1) : "memory");
    }
    __syncthreads();
    {
        const int   nbytes = (half == 0) ? HALF_T * 4 : XS_LEN * 4;
        const float* src   = (half == 0) ? xrow : (xrow + t_base - HALO);
        uint32_t dst = (uint32_t)__cvta_generic_to_shared(
                           (half == 0) ? (xs + HALO) : xs);
        if (tid == 0) {
            asm volatile("mbarrier.arrive.expect_tx.shared.b64 _, [%0], %1;"
                         :: "r"(mbar), "r"(nbytes) : "memory");
            asm volatile(
                "cp.async.bulk.shared::cluster.global.mbarrier::complete_tx::bytes "
                "[%0], [%1], %2, [%3];"
                :: "r"(dst), "l"(src), "r"(nbytes), "r"(mbar) : "memory");
        }
    }

    // constants overlap with the DMA
    const float af = __ldg(&a[f]);
    const float wf = __ldg(&w[f]);
    const float p498 = ipowf(af, WIN);
    const float Cw = (1.0f - af) / (1.0f - p498) * wf;
    const float a23 = ipowf(af, 23);
    const float a25 = a23 * af * af;

    // halo splat for the first half (disjoint from DMA destination)
    if (half == 0) {
        const float x0v = __ldg(&xrow[0]);
        const float4 pad4 = make_float4(x0v, x0v, x0v, x0v);
        float4* xs4 = (float4*)xs;
        #pragma unroll
        for (int i = tid; i < HALO / 4; i += BLOCK)
            xs4[i] = pad4;
    }

    // wait for DMA (parity 0)
    {
        uint32_t done;
        asm volatile(
            "{\n\t.reg .pred p;\n\t"
            "mbarrier.try_wait.parity.shared.b64 p, [%1], %2;\n\t"
            "selp.b32 %0, 1, 0, p;\n\t}"
            : "=r"(done) : "r"(mbar), "r"(0u) : "memory");
        while (!done) {
            asm volatile(
                "{\n\t.reg .pred p;\n\t"
                "mbarrier.try_wait.parity.shared.b64 p, [%1], %2, 0x989680;\n\t"
                "selp.b32 %0, 1, 0, p;\n\t}"
                : "=r"(done) : "r"(mbar), "r"(0u) : "memory");
        }
    }
    __syncthreads();   // also orders the halo splat for all readers

    // ---- phase B1: chunk Horner sums; workers cache their window in regs ----
    // chunk k covers xs[25k+2 .. 25k+26]; G_k = Horner(25), Hd_k = first 23 terms
    float r[LSUB];
    if (tid < NSUB) {
        const int base = 25 * tid + 2;
        #pragma unroll
        for (int s = 0; s < LSUB; ++s)
            r[s] = xs[base + s];
        float g = 0.f;
        #pragma unroll
        for (int s = 0; s < 23; ++s)
            g = fmaf(af, g, r[s]);
        sHd[tid] = g;
        g = fmaf(af, g, r[23]);
        g = fmaf(af, g, r[24]);
        sG[tid] = g;
    } else {
        const int k = tid - (BLOCK - NG + NSUB) + NSUB; // maps 173..191 -> 160..178
        if (k >= NSUB && k < NG) {
            const int base = 25 * k + 2;
            float g = 0.f;
            #pragma unroll
            for (int s = 0; s < 23; ++s)
                g = fmaf(af, g, xs[base + s]);
            sHd[k] = g;
            g = fmaf(af, g, xs[base + 23]);
            g = fmaf(af, g, xs[base + 24]);
            sG[k] = g;
        }
    }
    __syncthreads();

    // ---- phase B2: warm-up combine + sliding recurrence ----
    if (tid < NSUB) {
        float T = sG[tid];
        #pragma unroll
        for (int m = 1; m <= 18; ++m)
            T = fmaf(a25, T, sG[tid + m]);
        float S = fmaf(a23, T, sHd[tid + 19]);

        const int p0 = 25 * tid;
        #pragma unroll
        for (int s = 0; s < LSUB; ++s) {
            const float xt = xs[p0 + HALO + s];
            ys[p0 + s] = fabsf(fmaf(-Cw, S, xt));
            S = fmaf(af, S, fmaf(-p498, r[s], xt));   // xo from registers
        }
    }
    __syncthreads();

    // ---- phase C: bulk async store smem -> GMEM ----
    if (tid == 0) {
        uint32_t src = (uint32_t)__cvta_generic_to_shared(ys);
        asm volatile("fence.proxy.async.shared::cta;" ::: "memory");
        asm volatile("cp.async.bulk.global.shared::cta.bulk_group [%0], [%1], %2;"
                     :: "l"(orow), "r"(src), "r"(HALF_T * 4) : "memory");
        asm volatile("cp.async.bulk.commit_group;" ::: "memory");
        asm volatile("cp.async.bulk.wait_group 0;" ::: "memory");
    }
}

extern "C" void kernel_launch(void* const* d_in, const int* in_sizes, int n_in,
                              void* d_out, int out_size) {
    const float* x = (const float*)d_in[0];
    const float* a = (const float*)d_in[1];
    const float* w = (const float*)d_in[2];
    float* out = (float*)d_out;

    const int F = in_sizes[1];                 // 64
    const int rows = in_sizes[0] / T_LEN;      // 2048
    const int smem = (XS_LEN + HALF_T + 2 * 180) * (int)sizeof(float) + 16;

    cudaFuncSetAttribute(willmore_kernel,
                         cudaFuncAttributeMaxDynamicSharedMemorySize, smem);
    willmore_kernel<<<rows * 2, BLOCK, smem>>>(x, a, w, out, F);
}

// round 8
// speedup vs baseline: 3.0463x; 1.0064x over previous
#include <cuda_runtime.h>
#include <cstdint>

// x: (32,1,64,8000) fp32, a:(64,), w:(64,)
// y[b,f,t] = | x[t] - Cw * S_t |,  S_t = sum_{d=1}^{498} a^{d-1} x_edge[t-d]
// Cw = w*(1-a)/(1-a^498), edge pad x[j<0] -> x[0]
//
// One block per row; 4 tiles of 2000 samples (+500 halo), double-buffered
// TMA loads pipelined against compute. Chunked parallel warm-up (LSUB=25).
#define T_LEN   8000
#define TILE_T  2000
#define NTILE   4
#define HALO    500
#define XS_LEN  2500        // HALO + TILE_T
#define WIN     498
#define LSUB    25
#define NSUB    80          // workers per tile
#define NG      99          // chunk sums per tile
#define BLOCK   128
// float offsets inside dynamic smem (keep TMA/mbar targets 16B-aligned)
#define OFF_XS0  0
#define OFF_XS1  2500
#define OFF_YS   5000
#define OFF_SG   7000
#define OFF_SHD  7099
#define OFF_MBAR 7200       // byte 28800: 16B-aligned
#define SMEM_FLOATS 7204

__device__ __forceinline__ float ipowf(float base, int e) {
    float p = 1.0f;
    while (e) { if (e & 1) p *= base; base *= base; e >>= 1; }
    return p;
}

__device__ __forceinline__ void mbar_wait(uint32_t mbar, uint32_t parity) {
    uint32_t done;
    asm volatile(
        "{\n\t.reg .pred p;\n\t"
        "mbarrier.try_wait.parity.shared.b64 p, [%1], %2;\n\t"
        "selp.b32 %0, 1, 0, p;\n\t}"
        : "=r"(done) : "r"(mbar), "r"(parity) : "memory");
    while (!done) {
        asm volatile(
            "{\n\t.reg .pred p;\n\t"
            "mbarrier.try_wait.parity.shared.b64 p, [%1], %2, 0x989680;\n\t"
            "selp.b32 %0, 1, 0, p;\n\t}"
            : "=r"(done) : "r"(mbar), "r"(parity) : "memory");
    }
}

__global__ __launch_bounds__(BLOCK, 7)
void willmore_kernel(const float* __restrict__ x,
                     const float* __restrict__ a,
                     const float* __restrict__ w,
                     float* __restrict__ out,
                     int F) {
    extern __shared__ float sm[];
    float* xsb[2] = { sm + OFF_XS0, sm + OFF_XS1 };
    float* ys  = sm + OFF_YS;
    float* sG  = sm + OFF_SG;
    float* sHd = sm + OFF_SHD;
    const uint32_t mbar0 = (uint32_t)__cvta_generic_to_shared(sm + OFF_MBAR);
    const uint32_t mbar1 = mbar0 + 8;

    const int tid = threadIdx.x;
    const int row = blockIdx.x;
    const int f   = row % F;
    const float* __restrict__ xrow = x + (size_t)row * T_LEN;
    float*       __restrict__ orow = out + (size_t)row * T_LEN;

    if (tid == 0) {
        asm volatile("mbarrier.init.shared.b64 [%0], %1;" :: "r"(mbar0), "r"(1) : "memory");
        asm volatile("mbarrier.init.shared.b64 [%0], %1;" :: "r"(mbar1), "r"(1) : "memory");
    }

    // halo splat for tile 0 (disjoint from tile-0 DMA destination)
    {
        const float x0v = __ldg(&xrow[0]);
        const float4 pad4 = make_float4(x0v, x0v, x0v, x0v);
        float4* xs4 = (float4*)xsb[0];
        #pragma unroll
        for (int i = tid; i < HALO / 4; i += BLOCK)
            xs4[i] = pad4;
    }
    __syncthreads();   // mbar init + splat visible

    // issue DMA for tile 0
    if (tid == 0) {
        const int nbytes = TILE_T * 4;
        uint32_t dst = (uint32_t)__cvta_generic_to_shared(xsb[0] + HALO);
        asm volatile("mbarrier.arrive.expect_tx.shared.b64 _, [%0], %1;"
                     :: "r"(mbar0), "r"(nbytes) : "memory");
        asm volatile(
            "cp.async.bulk.shared::cluster.global.mbarrier::complete_tx::bytes "
            "[%0], [%1], %2, [%3];"
            :: "r"(dst), "l"(xrow), "r"(nbytes), "r"(mbar0) : "memory");
    }

    // constants (overlap DMA)
    const float af = __ldg(&a[f]);
    const float wf = __ldg(&w[f]);
    const float p498 = ipowf(af, WIN);
    const float Cw = (1.0f - af) / (1.0f - p498) * wf;
    const float a23 = ipowf(af, 23);
    const float a25 = a23 * af * af;

    #pragma unroll
    for (int q = 0; q < NTILE; ++q) {
        float* xs = xsb[q & 1];
        const uint32_t mbar = (q & 1) ? mbar1 : mbar0;

        // prefetch next tile into the other buffer (fully consumed in q-1;
        // the post-B2 __syncthreads of q-1 ordered all reads before this)
        if (tid == 0 && q + 1 < NTILE) {
            const uint32_t mb_n = ((q + 1) & 1) ? mbar1 : mbar0;
            const int nbytes = XS_LEN * 4;
            const float* src = xrow + (q + 1) * TILE_T - HALO;
            uint32_t dst = (uint32_t)__cvta_generic_to_shared(xsb[(q + 1) & 1]);
            asm volatile("mbarrier.arrive.expect_tx.shared.b64 _, [%0], %1;"
                         :: "r"(mb_n), "r"(nbytes) : "memory");
            asm volatile(
                "cp.async.bulk.shared::cluster.global.mbarrier::complete_tx::bytes "
                "[%0], [%1], %2, [%3];"
                :: "r"(dst), "l"(src), "r"(nbytes), "r"(mb_n) : "memory");
        }

        // wait for this tile's data (each mbar flips phase every 2 tiles)
        mbar_wait(mbar, (q >> 1) & 1);

        // ---- B1: chunk Horner sums; workers cache window in regs ----
        float r[LSUB];
        if (tid < NG) {
            const int base = 25 * tid + 2;
            if (tid < NSUB) {
                #pragma unroll
                for (int s = 0; s < LSUB; ++s)
                    r[s] = xs[base + s];
                float g = 0.f;
                #pragma unroll
                for (int s = 0; s < 23; ++s)
                    g = fmaf(af, g, r[s]);
                sHd[tid] = g;
                g = fmaf(af, g, r[23]);
                g = fmaf(af, g, r[24]);
                sG[tid] = g;
            } else {
                float g = 0.f;
                #pragma unroll
                for (int s = 0; s < 23; ++s)
                    g = fmaf(af, g, xs[base + s]);
                sHd[tid] = g;
                g = fmaf(af, g, xs[base + 23]);
                g = fmaf(af, g, xs[base + 24]);
                sG[tid] = g;
            }
        }
        // previous ys bulk-store must complete before B2 overwrites ys
        if (tid == 0 && q > 0)
            asm volatile("cp.async.bulk.wait_group 0;" ::: "memory");
        __syncthreads();

        // ---- B2: warm-up combine + sliding recurrence ----
        if (tid < NSUB) {
            float T = sG[tid];
            #pragma unroll
            for (int m = 1; m <= 18; ++m)
                T = fmaf(a25, T, sG[tid + m]);
            float S = fmaf(a23, T, sHd[tid + 19]);

            const int p0 = 25 * tid;
            #pragma unroll
            for (int s = 0; s < LSUB; ++s) {
                const float xt = xs[p0 + HALO + s];
                ys[p0 + s] = fabsf(fmaf(-Cw, S, xt));
                S = fmaf(af, S, fmaf(-p498, r[s], xt));
            }
        }
        __syncthreads();

        // ---- store tile outputs ----
        if (tid == 0) {
            uint32_t src = (uint32_t)__cvta_generic_to_shared(ys);
            asm volatile("fence.proxy.async.shared::cta;" ::: "memory");
            asm volatile("cp.async.bulk.global.shared::cta.bulk_group [%0], [%1], %2;"
                         :: "l"(orow + q * TILE_T), "r"(src), "r"(TILE_T * 4) : "memory");
            asm volatile("cp.async.bulk.commit_group;" ::: "memory");
        }
    }

    if (tid == 0)
        asm volatile("cp.async.bulk.wait_group 0;" ::: "memory");
}

extern "C" void kernel_launch(void* const* d_in, const int* in_sizes, int n_in,
                              void* d_out, int out_size) {
    const float* x = (const float*)d_in[0];
    const float* a = (const float*)d_in[1];
    const float* w = (const float*)d_in[2];
    float* out = (float*)d_out;

    const int F = in_sizes[1];                 // 64
    const int rows = in_sizes[0] / T_LEN;      // 2048
    const int smem = SMEM_FLOATS * (int)sizeof(float);

    cudaFuncSetAttribute(willmore_kernel,
                         cudaFuncAttributeMaxDynamicSharedMemorySize, smem);
    willmore_kernel<<<rows, BLOCK, smem>>>(x, a, w, out, F);
}